// round 2
// baseline (speedup 1.0000x reference)
#include <cuda_runtime.h>
#include <cstdint>

#define NSEG   512
#define HID    512
#define GOALD  128
#define INDIM  640
#define BLOCK  256
#define MROWS  512          // nodes per block (2 per thread)
#define KT     16           // k tile
#define XPAD   20           // padded row stride (words): conflict-free LDS.128 & STS
#define NTILES (INDIM / KT) // 40
#define BUFW   (MROWS * XPAD)
#define WS_OFF (2 * BUFW)                 // W1 after the two x buffers
#define SMEM_BYTES ((2 * BUFW + INDIM * 16) * 4)

typedef unsigned long long u64;

__device__ float    g_sum[NSEG];   // zero-initialized at module load;
__device__ float    g_cnt[NSEG];   // finalize re-zeros for next call
__device__ unsigned g_max[NSEG];

__device__ __forceinline__ void ffma2(u64 &acc, u64 a, u64 b) {
    asm("fma.rn.f32x2 %0, %1, %2, %0;" : "+l"(acc) : "l"(a), "l"(b));
}
__device__ __forceinline__ u64 pk2(float v) {
    u64 r; asm("mov.b64 %0, {%1, %1};" : "=l"(r) : "f"(v)); return r;
}
__device__ __forceinline__ float2 upk(u64 v) {
    float2 f; asm("mov.b64 {%0, %1}, %2;" : "=f"(f.x), "=f"(f.y) : "l"(v)); return f;
}
__device__ __forceinline__ void cp16(uint32_t dst, const void* src, bool pred) {
    int sz = pred ? 16 : 0;
    asm volatile("cp.async.cg.shared.global [%0], [%1], 16, %2;"
                 :: "r"(dst), "l"(src), "r"(sz));
}
__device__ __forceinline__ void cp_commit() {
    asm volatile("cp.async.commit_group;");
}
template <int M>
__device__ __forceinline__ void cp_wait() {
    asm volatile("cp.async.wait_group %0;" :: "n"(M));
}

__global__ __launch_bounds__(BLOCK) void mlp_seg_kernel(
    const float* __restrict__ nodes, const float* __restrict__ goal,
    const int* __restrict__ segids,
    const float* __restrict__ W1, const float* __restrict__ b1,
    const float* __restrict__ W2, const float* __restrict__ b2,
    int N)
{
    extern __shared__ float smem[];
    float* ws = smem + WS_OFF;           // [INDIM][16]
    const int t    = threadIdx.x;
    const int base = blockIdx.x * MROWS;

    const uint32_t smem_u32 = (uint32_t)__cvta_generic_to_shared(smem);

    // --- preload full W1 into smem (10240 floats, coalesced) ---
#pragma unroll
    for (int p = 0; p < INDIM * 16 / 4 / BLOCK; ++p)   // 10 float4 per thread
        ((float4*)ws)[p * BLOCK + t] = ((const float4*)W1)[p * BLOCK + t];

    // staging helper: tile -> buf (8 cp.async.cg per thread)
    const int lane = t & 31, warp = t >> 5;
    const int rloc = (warp << 3) + (lane & 7);   // 0..63
    const int cch  = lane >> 3;                  // chunk 0..3 (16B each)

    auto stage = [&](int tile, int buf) {
        const int k0 = tile * KT;
        const float* src; int stride, kloc;
        if (k0 < HID) { src = nodes; stride = HID;   kloc = k0; }
        else          { src = goal;  stride = GOALD; kloc = k0 - HID; }
#pragma unroll
        for (int pass = 0; pass < 8; ++pass) {
            int row  = pass * 64 + rloc;
            int node = base + row;
            const float* g = src + (size_t)node * stride + kloc + cch * 4;
            uint32_t d = smem_u32 + (uint32_t)((buf * BUFW + row * XPAD + cch * 4) << 2);
            cp16(d, g, node < N);
        }
        cp_commit();
    };

    u64 accA[8], accB[8];
#pragma unroll
    for (int p = 0; p < 8; ++p) { accA[p] = 0ull; accB[p] = 0ull; }

    // prologue: tile 0 in flight
    stage(0, 0);

    for (int tile = 0; tile < NTILES; ++tile) {
        if (tile + 1 < NTILES) { stage(tile + 1, (tile + 1) & 1); cp_wait<1>(); }
        else                   { cp_wait<0>(); }
        __syncthreads();

        const float* xbuf = smem + (tile & 1) * BUFW;
        const int    k0   = tile * KT;
#pragma unroll
        for (int kk = 0; kk < KT; kk += 4) {
            float4 xa = *(const float4*)(xbuf + t * XPAD + kk);
            float4 xb = *(const float4*)(xbuf + (t + BLOCK) * XPAD + kk);
            const float* wrow = ws + (k0 + kk) * 16;
#pragma unroll
            for (int r = 0; r < 4; ++r) {
                const ulonglong2* wr = (const ulonglong2*)(wrow + r * 16);
                ulonglong2 q0 = wr[0], q1 = wr[1], q2 = wr[2], q3 = wr[3];
                float fa = (r == 0) ? xa.x : (r == 1) ? xa.y : (r == 2) ? xa.z : xa.w;
                float fb = (r == 0) ? xb.x : (r == 1) ? xb.y : (r == 2) ? xb.z : xb.w;
                u64 va = pk2(fa), vb = pk2(fb);
                ffma2(accA[0], va, q0.x); ffma2(accA[1], va, q0.y);
                ffma2(accA[2], va, q1.x); ffma2(accA[3], va, q1.y);
                ffma2(accA[4], va, q2.x); ffma2(accA[5], va, q2.y);
                ffma2(accA[6], va, q3.x); ffma2(accA[7], va, q3.y);
                ffma2(accB[0], vb, q0.x); ffma2(accB[1], vb, q0.y);
                ffma2(accB[2], vb, q1.x); ffma2(accB[3], vb, q1.y);
                ffma2(accB[4], vb, q2.x); ffma2(accB[5], vb, q2.y);
                ffma2(accB[6], vb, q3.x); ffma2(accB[7], vb, q3.y);
            }
        }
        __syncthreads();
    }

    // --- epilogue: bias + relu + W2 dot, then segment atomics ---
    float w2r[16], b1r[16];
#pragma unroll
    for (int j = 0; j < 16; ++j) { b1r[j] = b1[j]; w2r[j] = W2[j]; }
    const float bias2 = b2[0];

    auto emit = [&](int node, u64* acc) {
        if (node >= N) return;
        float out = bias2;
#pragma unroll
        for (int p = 0; p < 8; ++p) {
            float2 a = upk(acc[p]);
            float h0 = fmaxf(a.x + b1r[2 * p],     0.f);
            float h1 = fmaxf(a.y + b1r[2 * p + 1], 0.f);
            out += h0 * w2r[2 * p] + h1 * w2r[2 * p + 1];
        }
        int seg = segids[node];
        atomicAdd(&g_sum[seg], out);
        atomicAdd(&g_cnt[seg], 1.f);
        unsigned b  = __float_as_uint(out);
        unsigned e  = (b & 0x80000000u) ? ~b : (b | 0x80000000u);
        atomicMax(&g_max[seg], e);
    };
    emit(base + t,         accA);
    emit(base + t + BLOCK, accB);
}

__global__ void finalize_kernel(float* __restrict__ out) {
    int s = threadIdx.x;
    if (s < NSEG) {
        float mean = g_sum[s] / fmaxf(g_cnt[s], 1.f);
        unsigned u = g_max[s];
        float mx = (u & 0x80000000u) ? __uint_as_float(u ^ 0x80000000u)
                                     : __uint_as_float(~u);
        out[s] = mx * 0.5f + mean * 0.5f;
        // re-zero accumulators for the next (graph-replayed) call
        g_sum[s] = 0.f;
        g_cnt[s] = 0.f;
        g_max[s] = 0u;
    }
}

extern "C" void kernel_launch(void* const* d_in, const int* in_sizes, int n_in,
                              void* d_out, int out_size) {
    const float* nodes  = (const float*)d_in[0];
    const float* goal   = (const float*)d_in[1];
    const int*   segids = (const int*)d_in[2];
    int iW = (in_sizes[3] == INDIM * 16) ? 3 : 4;   // num_segments may be absent
    const float* W1 = (const float*)d_in[iW];
    const float* b1 = (const float*)d_in[iW + 1];
    const float* W2 = (const float*)d_in[iW + 2];
    const float* b2 = (const float*)d_in[iW + 3];
    const int N = in_sizes[2];

    cudaFuncSetAttribute(mlp_seg_kernel,
                         cudaFuncAttributeMaxDynamicSharedMemorySize, SMEM_BYTES);

    int grid = (N + MROWS - 1) / MROWS;
    mlp_seg_kernel<<<grid, BLOCK, SMEM_BYTES>>>(nodes, goal, segids,
                                                W1, b1, W2, b2, N);
    finalize_kernel<<<1, NSEG>>>((float*)d_out);
}

// round 3
// speedup vs baseline: 1.0587x; 1.0587x over previous
#include <cuda_runtime.h>
#include <cstdint>

#define NSEG   512
#define HID    512
#define GOALD  128
#define INDIM  640
#define BLOCK  256
#define MROWS  256          // nodes per block
#define KT     16           // k tile (floats)
#define XPAD   20           // padded row stride (words): conflict-free LDS/STS
#define NTILES (INDIM / KT) // 40
#define BUFW   (MROWS * XPAD)
#define WS_OFF (2 * BUFW)
#define SMEM_BYTES ((2 * BUFW + INDIM * 16) * 4)   // 80 KB

typedef unsigned long long u64;

__device__ float    g_sum[NSEG];
__device__ float    g_cnt[NSEG];
__device__ unsigned g_max[NSEG];

__device__ __forceinline__ void ffma2(u64 &acc, u64 a, u64 b) {
    asm("fma.rn.f32x2 %0, %1, %2, %0;" : "+l"(acc) : "l"(a), "l"(b));
}
__device__ __forceinline__ u64 pk2(float v) {
    u64 r; asm("mov.b64 %0, {%1, %1};" : "=l"(r) : "f"(v)); return r;
}
__device__ __forceinline__ float2 upk(u64 v) {
    float2 f; asm("mov.b64 {%0, %1}, %2;" : "=f"(f.x), "=f"(f.y) : "l"(v)); return f;
}
__device__ __forceinline__ void cp16(uint32_t dst, const void* src, bool pred) {
    int sz = pred ? 16 : 0;
    asm volatile("cp.async.cg.shared.global [%0], [%1], 16, %2;"
                 :: "r"(dst), "l"(src), "r"(sz));
}
__device__ __forceinline__ void cp_commit() {
    asm volatile("cp.async.commit_group;");
}
template <int M>
__device__ __forceinline__ void cp_wait() {
    asm volatile("cp.async.wait_group %0;" :: "n"(M));
}

__global__ void noop_kernel() {}

__global__ __launch_bounds__(BLOCK, 2) void mlp_seg_kernel(
    const float* __restrict__ nodes, const float* __restrict__ goal,
    const int* __restrict__ segids,
    const float* __restrict__ W1, const float* __restrict__ b1,
    const float* __restrict__ W2, const float* __restrict__ b2,
    int N)
{
    extern __shared__ float smem[];
    float* ws = smem + WS_OFF;           // [INDIM][16]
    const int t    = threadIdx.x;
    const int base = blockIdx.x * MROWS;
    const int lane = t & 31, warp = t >> 5;
    const int jh   = t >> 7;             // j-half: 0 -> j0..7, 1 -> j8..15
    const int row0 = t & 127;            // this thread's node rows: row0, row0+128

    const uint32_t smem_u32 = (uint32_t)__cvta_generic_to_shared(smem);

    // --- preload full W1 (10240 floats) ---
#pragma unroll
    for (int p = 0; p < INDIM * 16 / 4 / BLOCK; ++p)
        ((float4*)ws)[p * BLOCK + t] = ((const float4*)W1)[p * BLOCK + t];

    // staging: 256 rows x 4 chunks(16B) = 1024 tasks, 4 per thread
    const int srow = warp * 8 + (lane & 7);  // 0..63  (banks 20r%32 distinct per phase)
    const int cch  = lane >> 3;              // 0..3

    auto stage = [&](int tile, int buf) {
        const int k0 = tile * KT;
        const float* src; int stride, kloc;
        if (k0 < HID) { src = nodes; stride = HID;   kloc = k0; }
        else          { src = goal;  stride = GOALD; kloc = k0 - HID; }
#pragma unroll
        for (int pass = 0; pass < 4; ++pass) {
            int row  = pass * 64 + srow;
            int node = base + row;
            const float* g = src + (size_t)node * stride + kloc + cch * 4;
            uint32_t d = smem_u32 + (uint32_t)((buf * BUFW + row * XPAD + cch * 4) << 2);
            cp16(d, g, node < N);
        }
        cp_commit();
    };

    u64 accA[4], accB[4];
#pragma unroll
    for (int p = 0; p < 4; ++p) { accA[p] = 0ull; accB[p] = 0ull; }

    stage(0, 0);

    for (int tile = 0; tile < NTILES; ++tile) {
        if (tile + 1 < NTILES) { stage(tile + 1, (tile + 1) & 1); cp_wait<1>(); }
        else                   { cp_wait<0>(); }
        __syncthreads();

        const float* xbuf = smem + (tile & 1) * BUFW;
        const float* wbas = ws + tile * KT * 16 + jh * 8;
#pragma unroll
        for (int kk = 0; kk < KT; kk += 4) {
            float4 xa = *(const float4*)(xbuf + row0 * XPAD + kk);
            float4 xb = *(const float4*)(xbuf + (row0 + 128) * XPAD + kk);
#pragma unroll
            for (int r = 0; r < 4; ++r) {
                const ulonglong2* wr = (const ulonglong2*)(wbas + (kk + r) * 16);
                ulonglong2 q = wr[0];          // j 0..3 of this half
                ulonglong2 p = wr[1];          // j 4..7 of this half
                float fa = (r == 0) ? xa.x : (r == 1) ? xa.y : (r == 2) ? xa.z : xa.w;
                float fb = (r == 0) ? xb.x : (r == 1) ? xb.y : (r == 2) ? xb.z : xb.w;
                u64 va = pk2(fa), vb = pk2(fb);
                ffma2(accA[0], va, q.x); ffma2(accA[1], va, q.y);
                ffma2(accA[2], va, p.x); ffma2(accA[3], va, p.y);
                ffma2(accB[0], vb, q.x); ffma2(accB[1], vb, q.y);
                ffma2(accB[2], vb, p.x); ffma2(accB[3], vb, p.y);
            }
        }
        __syncthreads();
    }

    // --- epilogue: bias + relu + W2 dot (per j-half), cross-half reduce ---
    float w2r[8], b1r[8];
#pragma unroll
    for (int j = 0; j < 8; ++j) { b1r[j] = b1[jh * 8 + j]; w2r[j] = W2[jh * 8 + j]; }

    float part[2];
#pragma unroll
    for (int n = 0; n < 2; ++n) {
        u64* acc = n ? accB : accA;
        float s = 0.f;
#pragma unroll
        for (int p = 0; p < 4; ++p) {
            float2 a = upk(acc[p]);
            s += fmaxf(a.x + b1r[2 * p],     0.f) * w2r[2 * p];
            s += fmaxf(a.y + b1r[2 * p + 1], 0.f) * w2r[2 * p + 1];
        }
        part[n] = s;
    }

    float* red = smem;   // reuse x buffers
    if (jh == 1) { red[row0] = part[0]; red[row0 + 128] = part[1]; }
    __syncthreads();
    if (jh == 0) {
        const float bias2 = b2[0];
#pragma unroll
        for (int n = 0; n < 2; ++n) {
            int node = base + row0 + n * 128;
            if (node < N) {
                float out = part[n] + red[row0 + n * 128] + bias2;
                int seg = segids[node];
                atomicAdd(&g_sum[seg], out);
                atomicAdd(&g_cnt[seg], 1.f);
                unsigned b = __float_as_uint(out);
                unsigned e = (b & 0x80000000u) ? ~b : (b | 0x80000000u);
                atomicMax(&g_max[seg], e);
            }
        }
    }
}

__global__ void finalize_kernel(float* __restrict__ out) {
    int s = threadIdx.x;
    if (s < NSEG) {
        float mean = g_sum[s] / fmaxf(g_cnt[s], 1.f);
        unsigned u = g_max[s];
        float mx = (u & 0x80000000u) ? __uint_as_float(u ^ 0x80000000u)
                                     : __uint_as_float(~u);
        out[s] = mx * 0.5f + mean * 0.5f;
        g_sum[s] = 0.f; g_cnt[s] = 0.f; g_max[s] = 0u;
    }
}

extern "C" void kernel_launch(void* const* d_in, const int* in_sizes, int n_in,
                              void* d_out, int out_size) {
    const float* nodes  = (const float*)d_in[0];
    const float* goal   = (const float*)d_in[1];
    const int*   segids = (const int*)d_in[2];
    int iW = (in_sizes[3] == INDIM * 16) ? 3 : 4;
    const float* W1 = (const float*)d_in[iW];
    const float* b1 = (const float*)d_in[iW + 1];
    const float* W2 = (const float*)d_in[iW + 2];
    const float* b2 = (const float*)d_in[iW + 3];
    const int N = in_sizes[2];

    cudaFuncSetAttribute(mlp_seg_kernel,
                         cudaFuncAttributeMaxDynamicSharedMemorySize, SMEM_BYTES);

    int grid = (N + MROWS - 1) / MROWS;
    // launch pattern [noop, mlp, noop, fin] -> ncu -s 5 lands on mlp (idx 5)
    noop_kernel<<<1, 1>>>();
    mlp_seg_kernel<<<grid, BLOCK, SMEM_BYTES>>>(nodes, goal, segids,
                                                W1, b1, W2, b2, N);
    noop_kernel<<<1, 1>>>();
    finalize_kernel<<<1, NSEG>>>((float*)d_out);
}